// round 3
// baseline (speedup 1.0000x reference)
#include <cuda_runtime.h>
#include <math.h>

#define BATCH 8
#define CHAN 128
#define PLANE 65536          // D*H*W = 4*128*128
#define NBC (BATCH * CHAN)   // 1024

__device__ float g_max[NBC];
__device__ float g_gate[NBC];
__device__ unsigned int g_cnt = 0;

// ---------------------------------------------------------------------------
// Kernel 1: per-(b,c) max reduce over each 65536-elem plane, PLUS the tiny
// MLP gate computed by the last block to finish (threadfence-reduction
// pattern) -- removes the single-block mlp kernel bubble entirely.
// ---------------------------------------------------------------------------
__global__ __launch_bounds__(512) void reduce_mlp_kernel(const float* __restrict__ x,
                                                         const float* __restrict__ w1,
                                                         const float* __restrict__ b1,
                                                         const float* __restrict__ w2,
                                                         const float* __restrict__ b2) {
    const int bc = blockIdx.x;
    const float4* p = reinterpret_cast<const float4*>(x) + (size_t)bc * (PLANE / 4);
    const int tid = threadIdx.x;

    float m0 = -INFINITY, m1 = -INFINITY;
    #pragma unroll 4
    for (int i = tid; i < PLANE / 4; i += 1024) {
        float4 a = __ldcs(p + i);
        float4 b = __ldcs(p + i + 512);
        m0 = fmaxf(m0, fmaxf(fmaxf(a.x, a.y), fmaxf(a.z, a.w)));
        m1 = fmaxf(m1, fmaxf(fmaxf(b.x, b.y), fmaxf(b.z, b.w)));
    }
    float m = fmaxf(m0, m1);

    #pragma unroll
    for (int off = 16; off > 0; off >>= 1)
        m = fmaxf(m, __shfl_xor_sync(0xffffffffu, m, off));

    __shared__ float sm[16];
    __shared__ int s_last;
    if ((tid & 31) == 0) sm[tid >> 5] = m;
    __syncthreads();
    if (tid < 16) {
        m = sm[tid];
        #pragma unroll
        for (int off = 8; off > 0; off >>= 1)
            m = fmaxf(m, __shfl_xor_sync(0x0000ffffu, m, off));
        if (tid == 0) g_max[bc] = m;
    }

    // ---- last-block election ----
    if (tid == 0) {
        __threadfence();
        unsigned int old = atomicAdd(&g_cnt, 1u);
        s_last = (old == NBC - 1);
    }
    __syncthreads();
    if (!s_last) return;

    // ---- MLP gate (whole-GPU work is done; this block alone computes it) ----
    __shared__ float gp[BATCH][CHAN];
    __shared__ float hs[BATCH][CHAN];
    __threadfence();
    for (int i = tid; i < NBC; i += 512)
        gp[i / CHAN][i % CHAN] = __ldcg(&g_max[i]);
    __syncthreads();

    const int o = tid;          // threads 0..127 = output channel
    float acc[BATCH];
    if (o < CHAN) {
        const float bb = b1[o];
        #pragma unroll
        for (int b = 0; b < BATCH; b++) acc[b] = bb;
        const float* wrow = w1 + (size_t)o * CHAN;
        for (int c = 0; c < CHAN; c++) {
            const float w = wrow[c];
            #pragma unroll
            for (int b = 0; b < BATCH; b++) acc[b] = fmaf(gp[b][c], w, acc[b]);
        }
        #pragma unroll
        for (int b = 0; b < BATCH; b++) hs[b][o] = fmaxf(acc[b], 0.0f);
    }
    __syncthreads();
    if (o < CHAN) {
        const float bb = b2[o];
        #pragma unroll
        for (int b = 0; b < BATCH; b++) acc[b] = bb;
        const float* wrow = w2 + (size_t)o * CHAN;
        for (int c = 0; c < CHAN; c++) {
            const float w = wrow[c];
            #pragma unroll
            for (int b = 0; b < BATCH; b++) acc[b] = fmaf(hs[b][c], w, acc[b]);
        }
        #pragma unroll
        for (int b = 0; b < BATCH; b++)
            g_gate[b * CHAN + o] = 1.0f / (1.0f + expf(-acc[b]));
    }
    // reset counter for the next graph replay
    if (tid == 0) { __threadfence(); g_cnt = 0u; }
}

// ---------------------------------------------------------------------------
// Kernel 2: out = x * gate[bc].
// 256 threads x 8 float4 = 2048 consecutive float4 per block (1/8 plane), so
// the gate is block-uniform. 8 front-batched streaming loads per thread to
// maximize memory-level parallelism under the mixed read+write stream.
// ---------------------------------------------------------------------------
__global__ __launch_bounds__(256) void scale_kernel(const float* __restrict__ x,
                                                    float* __restrict__ out) {
    const float g = g_gate[blockIdx.x >> 3];     // 8 blocks per (b,c) plane
    const size_t base = (size_t)blockIdx.x * 2048 + threadIdx.x;
    const float4* xp = reinterpret_cast<const float4*>(x);
    float4* op = reinterpret_cast<float4*>(out);

    float4 v[8];
    #pragma unroll
    for (int k = 0; k < 8; k++)
        v[k] = __ldcs(xp + base + (size_t)k * 256);

    #pragma unroll
    for (int k = 0; k < 8; k++) {
        v[k].x *= g; v[k].y *= g; v[k].z *= g; v[k].w *= g;
        __stcs(op + base + (size_t)k * 256, v[k]);
    }
}

// ---------------------------------------------------------------------------
extern "C" void kernel_launch(void* const* d_in, const int* in_sizes, int n_in,
                              void* d_out, int out_size) {
    const float* x  = (const float*)d_in[0];
    const float* w1 = (const float*)d_in[1];
    const float* b1 = (const float*)d_in[2];
    const float* w2 = (const float*)d_in[3];
    const float* b2 = (const float*)d_in[4];
    float* out = (float*)d_out;

    reduce_mlp_kernel<<<NBC, 512>>>(x, w1, b1, w2, b2);
    // total float4: 16,777,216 -> 8192 blocks x (256 threads x 8 f4)
    scale_kernel<<<8192, 256>>>(x, out);
}

// round 4
// speedup vs baseline: 1.1084x; 1.1084x over previous
#include <cuda_runtime.h>
#include <math.h>

#define BATCH 8
#define CHAN 128
#define PLANE 65536          // D*H*W = 4*128*128
#define NBC (BATCH * CHAN)   // 1024

__device__ float g_max[NBC];
__device__ float g_gate[NBC];
__device__ unsigned int g_cnt = 0;

// ---------------------------------------------------------------------------
// Kernel 1: per-(b,c) max reduce + last-block MLP tail.
// __launch_bounds__(512, 4) caps regs at 32 so the MLP tail cannot depress
// the streaming reduce phase's occupancy (R3 lesson: tail code raised regs,
// occupancy fell, reduce went 40 -> 91 us). Spills, if any, hit only the
// single tail block.
// ---------------------------------------------------------------------------
__global__ __launch_bounds__(512, 4) void reduce_mlp_kernel(const float* __restrict__ x,
                                                            const float* __restrict__ w1,
                                                            const float* __restrict__ b1,
                                                            const float* __restrict__ w2,
                                                            const float* __restrict__ b2) {
    const int bc = blockIdx.x;
    const float4* p = reinterpret_cast<const float4*>(x) + (size_t)bc * (PLANE / 4);
    const int tid = threadIdx.x;

    float m0 = -INFINITY, m1 = -INFINITY;
    #pragma unroll 4
    for (int i = tid; i < PLANE / 4; i += 1024) {
        float4 a = __ldcs(p + i);
        float4 b = __ldcs(p + i + 512);
        m0 = fmaxf(m0, fmaxf(fmaxf(a.x, a.y), fmaxf(a.z, a.w)));
        m1 = fmaxf(m1, fmaxf(fmaxf(b.x, b.y), fmaxf(b.z, b.w)));
    }
    float m = fmaxf(m0, m1);

    #pragma unroll
    for (int off = 16; off > 0; off >>= 1)
        m = fmaxf(m, __shfl_xor_sync(0xffffffffu, m, off));

    __shared__ float sm[16];
    __shared__ int s_last;
    if ((tid & 31) == 0) sm[tid >> 5] = m;
    __syncthreads();
    if (tid < 16) {
        m = sm[tid];
        #pragma unroll
        for (int off = 8; off > 0; off >>= 1)
            m = fmaxf(m, __shfl_xor_sync(0x0000ffffu, m, off));
        if (tid == 0) g_max[bc] = m;
    }

    // ---- last-block election ----
    if (tid == 0) {
        __threadfence();
        unsigned int old = atomicAdd(&g_cnt, 1u);
        s_last = (old == NBC - 1);
    }
    __syncthreads();
    if (!s_last) return;

    // ---- MLP gate: exactly one block reaches here, after all maxes landed ----
    __shared__ float gp[BATCH][CHAN];
    __shared__ float hs[BATCH][CHAN];
    __threadfence();
    for (int i = tid; i < NBC; i += 512)
        gp[i / CHAN][i % CHAN] = __ldcg(&g_max[i]);
    __syncthreads();

    const int o = tid;          // threads 0..127 = output channel
    float acc[BATCH];
    if (o < CHAN) {
        const float bb = b1[o];
        #pragma unroll
        for (int b = 0; b < BATCH; b++) acc[b] = bb;
        const float* wrow = w1 + (size_t)o * CHAN;
        for (int c = 0; c < CHAN; c++) {
            const float w = wrow[c];
            #pragma unroll
            for (int b = 0; b < BATCH; b++) acc[b] = fmaf(gp[b][c], w, acc[b]);
        }
        #pragma unroll
        for (int b = 0; b < BATCH; b++) hs[b][o] = fmaxf(acc[b], 0.0f);
    }
    __syncthreads();
    if (o < CHAN) {
        const float bb = b2[o];
        #pragma unroll
        for (int b = 0; b < BATCH; b++) acc[b] = bb;
        const float* wrow = w2 + (size_t)o * CHAN;
        for (int c = 0; c < CHAN; c++) {
            const float w = wrow[c];
            #pragma unroll
            for (int b = 0; b < BATCH; b++) acc[b] = fmaf(hs[b][c], w, acc[b]);
        }
        #pragma unroll
        for (int b = 0; b < BATCH; b++)
            g_gate[b * CHAN + o] = 1.0f / (1.0f + expf(-acc[b]));
    }
    // reset counter for the next graph replay
    if (tid == 0) { __threadfence(); g_cnt = 0u; }
}

// ---------------------------------------------------------------------------
// Kernel 2: out = x * gate[bc].  (unchanged from R3: 79 us, ~ceiling)
// 256 threads x 8 float4 = 2048 consecutive float4 per block (1/8 plane);
// gate is block-uniform; 8 front-batched streaming loads per thread.
// ---------------------------------------------------------------------------
__global__ __launch_bounds__(256) void scale_kernel(const float* __restrict__ x,
                                                    float* __restrict__ out) {
    const float g = g_gate[blockIdx.x >> 3];     // 8 blocks per (b,c) plane
    const size_t base = (size_t)blockIdx.x * 2048 + threadIdx.x;
    const float4* xp = reinterpret_cast<const float4*>(x);
    float4* op = reinterpret_cast<float4*>(out);

    float4 v[8];
    #pragma unroll
    for (int k = 0; k < 8; k++)
        v[k] = __ldcs(xp + base + (size_t)k * 256);

    #pragma unroll
    for (int k = 0; k < 8; k++) {
        v[k].x *= g; v[k].y *= g; v[k].z *= g; v[k].w *= g;
        __stcs(op + base + (size_t)k * 256, v[k]);
    }
}

// ---------------------------------------------------------------------------
extern "C" void kernel_launch(void* const* d_in, const int* in_sizes, int n_in,
                              void* d_out, int out_size) {
    const float* x  = (const float*)d_in[0];
    const float* w1 = (const float*)d_in[1];
    const float* b1 = (const float*)d_in[2];
    const float* w2 = (const float*)d_in[3];
    const float* b2 = (const float*)d_in[4];
    float* out = (float*)d_out;

    reduce_mlp_kernel<<<NBC, 512>>>(x, w1, b1, w2, b2);
    // total float4: 16,777,216 -> 8192 blocks x (256 threads x 8 f4)
    scale_kernel<<<8192, 256>>>(x, out);
}

// round 5
// speedup vs baseline: 1.2173x; 1.0982x over previous
#include <cuda_runtime.h>
#include <math.h>

#define BATCH 8
#define CHAN 128
#define PLANE 65536          // D*H*W = 4*128*128
#define NBC (BATCH * CHAN)   // 1024

__device__ float g_max[NBC];
__device__ float g_gate[NBC];

// ---------------------------------------------------------------------------
// Kernel 1: per-(b,c) global max (EXACT R2 kernel: 40.4us, 84% of HBM spec).
// ---------------------------------------------------------------------------
__global__ __launch_bounds__(512) void reduce_max_kernel(const float* __restrict__ x) {
    const int bc = blockIdx.x;
    const float4* p = reinterpret_cast<const float4*>(x) + (size_t)bc * (PLANE / 4);
    const int tid = threadIdx.x;

    float m0 = -INFINITY, m1 = -INFINITY;
    #pragma unroll 4
    for (int i = tid; i < PLANE / 4; i += 1024) {
        float4 a = __ldcs(p + i);
        float4 b = __ldcs(p + i + 512);
        m0 = fmaxf(m0, fmaxf(fmaxf(a.x, a.y), fmaxf(a.z, a.w)));
        m1 = fmaxf(m1, fmaxf(fmaxf(b.x, b.y), fmaxf(b.z, b.w)));
    }
    float m = fmaxf(m0, m1);

    #pragma unroll
    for (int off = 16; off > 0; off >>= 1)
        m = fmaxf(m, __shfl_xor_sync(0xffffffffu, m, off));

    __shared__ float sm[16];
    if ((tid & 31) == 0) sm[tid >> 5] = m;
    __syncthreads();
    if (tid < 16) {
        m = sm[tid];
        #pragma unroll
        for (int off = 8; off > 0; off >>= 1)
            m = fmaxf(m, __shfl_xor_sync(0x0000ffffu, m, off));
        if (tid == 0) g_max[bc] = m;
    }
}

// ---------------------------------------------------------------------------
// Kernel 2: tiny MLP gate, latency-optimized.
// 256 threads. Phase 1: pair (o, bh) = (tid&127, tid>>7); each thread does
// 4 batches for its channel, weight row loaded as 32 float4 (high MLP).
// Phase 2: 128 threads, each one output channel, all 8 batches.
// ---------------------------------------------------------------------------
__global__ __launch_bounds__(256) void mlp_kernel(const float* __restrict__ w1,
                                                  const float* __restrict__ b1,
                                                  const float* __restrict__ w2,
                                                  const float* __restrict__ b2) {
    __shared__ float gp[BATCH][CHAN];
    __shared__ float hs[BATCH][CHAN];
    const int tid = threadIdx.x;
    const int o = tid & 127;
    const int bh = tid >> 7;            // 0 or 1 -> batches [0..3] or [4..7]

    // load all 1024 maxes (4 per thread, coalesced)
    for (int i = tid; i < NBC; i += 256)
        gp[i >> 7][i & 127] = g_max[i];
    __syncthreads();

    // Phase 1: h = relu(gp @ w1^T + b1); thread handles 4 batches of channel o
    {
        const int b0 = bh * 4;
        float a0 = b1[o], a1 = a0, a2 = a0, a3 = a0;
        const float4* wrow = reinterpret_cast<const float4*>(w1 + (size_t)o * CHAN);
        #pragma unroll 8
        for (int q = 0; q < CHAN / 4; q++) {
            float4 w = wrow[q];
            const int c = q * 4;
            a0 = fmaf(gp[b0+0][c], w.x, a0); a0 = fmaf(gp[b0+0][c+1], w.y, a0);
            a0 = fmaf(gp[b0+0][c+2], w.z, a0); a0 = fmaf(gp[b0+0][c+3], w.w, a0);
            a1 = fmaf(gp[b0+1][c], w.x, a1); a1 = fmaf(gp[b0+1][c+1], w.y, a1);
            a1 = fmaf(gp[b0+1][c+2], w.z, a1); a1 = fmaf(gp[b0+1][c+3], w.w, a1);
            a2 = fmaf(gp[b0+2][c], w.x, a2); a2 = fmaf(gp[b0+2][c+1], w.y, a2);
            a2 = fmaf(gp[b0+2][c+2], w.z, a2); a2 = fmaf(gp[b0+2][c+3], w.w, a2);
            a3 = fmaf(gp[b0+3][c], w.x, a3); a3 = fmaf(gp[b0+3][c+1], w.y, a3);
            a3 = fmaf(gp[b0+3][c+2], w.z, a3); a3 = fmaf(gp[b0+3][c+3], w.w, a3);
        }
        hs[b0+0][o] = fmaxf(a0, 0.0f);
        hs[b0+1][o] = fmaxf(a1, 0.0f);
        hs[b0+2][o] = fmaxf(a2, 0.0f);
        hs[b0+3][o] = fmaxf(a3, 0.0f);
    }
    __syncthreads();

    // Phase 2: gate = sigmoid(hs @ w2^T + b2); thread handles 4 batches
    {
        const int b0 = bh * 4;
        float a0 = b2[o], a1 = a0, a2 = a0, a3 = a0;
        const float4* wrow = reinterpret_cast<const float4*>(w2 + (size_t)o * CHAN);
        #pragma unroll 8
        for (int q = 0; q < CHAN / 4; q++) {
            float4 w = wrow[q];
            const int c = q * 4;
            a0 = fmaf(hs[b0+0][c], w.x, a0); a0 = fmaf(hs[b0+0][c+1], w.y, a0);
            a0 = fmaf(hs[b0+0][c+2], w.z, a0); a0 = fmaf(hs[b0+0][c+3], w.w, a0);
            a1 = fmaf(hs[b0+1][c], w.x, a1); a1 = fmaf(hs[b0+1][c+1], w.y, a1);
            a1 = fmaf(hs[b0+1][c+2], w.z, a1); a1 = fmaf(hs[b0+1][c+3], w.w, a1);
            a2 = fmaf(hs[b0+2][c], w.x, a2); a2 = fmaf(hs[b0+2][c+1], w.y, a2);
            a2 = fmaf(hs[b0+2][c+2], w.z, a2); a2 = fmaf(hs[b0+2][c+3], w.w, a2);
            a3 = fmaf(hs[b0+3][c], w.x, a3); a3 = fmaf(hs[b0+3][c+1], w.y, a3);
            a3 = fmaf(hs[b0+3][c+2], w.z, a3); a3 = fmaf(hs[b0+3][c+3], w.w, a3);
        }
        g_gate[(b0+0) * CHAN + o] = 1.0f / (1.0f + expf(-a0));
        g_gate[(b0+1) * CHAN + o] = 1.0f / (1.0f + expf(-a1));
        g_gate[(b0+2) * CHAN + o] = 1.0f / (1.0f + expf(-a2));
        g_gate[(b0+3) * CHAN + o] = 1.0f / (1.0f + expf(-a3));
    }
}

// ---------------------------------------------------------------------------
// Kernel 3: out = x * gate[bc].  (EXACT R4 kernel: 75.5us, 79.6% of spec)
// ---------------------------------------------------------------------------
__global__ __launch_bounds__(256) void scale_kernel(const float* __restrict__ x,
                                                    float* __restrict__ out) {
    const float g = g_gate[blockIdx.x >> 3];     // 8 blocks per (b,c) plane
    const size_t base = (size_t)blockIdx.x * 2048 + threadIdx.x;
    const float4* xp = reinterpret_cast<const float4*>(x);
    float4* op = reinterpret_cast<float4*>(out);

    float4 v[8];
    #pragma unroll
    for (int k = 0; k < 8; k++)
        v[k] = __ldcs(xp + base + (size_t)k * 256);

    #pragma unroll
    for (int k = 0; k < 8; k++) {
        v[k].x *= g; v[k].y *= g; v[k].z *= g; v[k].w *= g;
        __stcs(op + base + (size_t)k * 256, v[k]);
    }
}

// ---------------------------------------------------------------------------
extern "C" void kernel_launch(void* const* d_in, const int* in_sizes, int n_in,
                              void* d_out, int out_size) {
    const float* x  = (const float*)d_in[0];
    const float* w1 = (const float*)d_in[1];
    const float* b1 = (const float*)d_in[2];
    const float* w2 = (const float*)d_in[3];
    const float* b2 = (const float*)d_in[4];
    float* out = (float*)d_out;

    reduce_max_kernel<<<NBC, 512>>>(x);
    mlp_kernel<<<1, 256>>>(w1, b1, w2, b2);
    scale_kernel<<<8192, 256>>>(x, out);
}